// round 6
// baseline (speedup 1.0000x reference)
#include <cuda_runtime.h>

#define BATCH 32
#define NCH   4
#define HH    512
#define WW    512
#define PLANE (HH*WW)          /* 262144 */
#define NSTEPS 8
#define D_SCALE 0.2f
#define RHO_SCALE 0.1f
#define RPW 16                  /* rows per warp */
#define WPB 8                   /* warps per block */

// Ping-pong scratch for the evolving channel-0 field (2 x 32 MiB).
__device__ float g_buf0[BATCH * PLANE];
__device__ float g_buf1[BATCH * PLANE];
// Per-step channel-0 sums: slot s = sum of field entering step s.
__device__ float g_sum0[(NSTEPS + 1) * BATCH];
// Constant sums of channels 1..3 (index (c-1)*BATCH + b).
__device__ float g_sumc[3 * BATCH];

__global__ void zero_sums_kernel() {
    int i = threadIdx.x;
    if (i < (NSTEPS + 1) * BATCH) g_sum0[i] = 0.0f;
    if (i < 3 * BATCH)            g_sumc[i] = 0.0f;
}

// Copy channels 1..3 input->output, reduce per-(batch,channel) sums.
// grid = (PLANE/4/256, BATCH*NCH), block = 256. Each thread: one float4.
__global__ void init_kernel(const float* __restrict__ x, float* __restrict__ out) {
    const int p = blockIdx.y;            // plane id = b*4 + c
    const int b = p >> 2;
    const int c = p & 3;
    const int i = blockIdx.x * blockDim.x + threadIdx.x;   // 0..65535

    const float4* src = (const float4*)(x + (size_t)p * PLANE);
    float4 v = src[i];
    if (c != 0) {
        ((float4*)(out + (size_t)p * PLANE))[i] = v;
    }
    float s = (v.x + v.y) + (v.z + v.w);

    #pragma unroll
    for (int o = 16; o > 0; o >>= 1) s += __shfl_down_sync(0xffffffffu, s, o);
    __shared__ float ws[8];
    const int lane = threadIdx.x & 31;
    const int w    = threadIdx.x >> 5;
    if (lane == 0) ws[w] = s;
    __syncthreads();
    if (w == 0) {
        s = (lane < 8) ? ws[lane] : 0.0f;
        #pragma unroll
        for (int o = 4; o > 0; o >>= 1) s += __shfl_down_sync(0x000000ffu, s, o);
        if (lane == 0) {
            if (c == 0) atomicAdd(&g_sum0[0 * BATCH + b], s);
            else        atomicAdd(&g_sumc[(c - 1) * BATCH + b], s);
        }
    }
}

// One reaction-diffusion step on channel 0 for all batches.
// Warp owns a 128-float column chunk (1 float4/lane), register-rolls RPW=16 rows.
// Periodic chunk-edge values for ALL 16 rows are prefetched at strip start
// (lanes 0-15: left edges, lanes 16-31: right edges) -> zero in-loop scalar
// loads; per-iteration edges come from register shuffles.
// grid = (4*HH/RPW/WPB, BATCH) = (16, 32) = 512 blocks -> single wave.
__global__ __launch_bounds__(256) void step_kernel(
        const float* __restrict__ src, int src_bstride,
        float* __restrict__ dst, int dst_bstride,
        const float* __restrict__ Wm,
        const float* __restrict__ bias,
        const int* __restrict__ t, int step) {
    const int b    = blockIdx.y;
    const int lane = threadIdx.x & 31;
    const int wid  = threadIdx.x >> 5;

    // --- Derive D, rho from previous-step sums ---
    const float inv = 1.0f / (float)PLANE;
    const float f0 = g_sum0[step * BATCH + b] * inv;
    const float f1 = g_sumc[0 * BATCH + b] * inv;
    const float f2 = g_sumc[1 * BATCH + b] * inv;
    const float f3 = g_sumc[2 * BATCH + b] * inv;
    const float z0 = f0 * Wm[0] + f1 * Wm[2] + f2 * Wm[4] + f3 * Wm[6] + bias[0];
    const float z1 = f0 * Wm[1] + f1 * Wm[3] + f2 * Wm[5] + f3 * Wm[7] + bias[1];
    float D   = D_SCALE   / (1.0f + expf(-z0));
    float rho = RHO_SCALE / (1.0f + expf(-z1));
    if (t[b] <= step) { D = 0.0f; rho = 0.0f; }   // mask off -> exact identity

    const float* __restrict__ u = src + (size_t)b * src_bstride;
    float* __restrict__ v       = dst + (size_t)b * dst_bstride;

    const int w     = blockIdx.x * WPB + wid;   // 0..127
    const int chunk = w & 3;                    // x chunk (128 floats)
    const int strip = w >> 2;                   // 0..31
    const int y0    = strip * RPW;
    const int xb    = chunk << 7;               // chunk base x
    const int x4    = xb + (lane << 2);         // this lane's float4 x
    const int xl    = (xb + WW - 1) & (WW - 1); // periodic left-edge x
    const int xr    = (xb + 128) & (WW - 1);    // periodic right-edge x

    // Prefetch all periodic edge scalars for this strip's RPW rows.
    // lanes 0..15: left edge of rows y0..y0+15; lanes 16..31: right edge.
    const int erow = (y0 + (lane & 15)) << 9;   // y0+15 <= 511, no wrap needed
    const float edge = (lane < 16) ? u[erow + xl] : u[erow + xr];

    float4 P = *(const float4*)(u + (((y0 + HH - 1) & (HH - 1)) << 9) + x4);
    float4 C = *(const float4*)(u + (y0 << 9) + x4);
    float4 N = *(const float4*)(u + ((y0 + 1) << 9) + x4);

    float ssum = 0.0f;

    #pragma unroll
    for (int i = 0; i < RPW; i++) {
        const int y   = y0 + i;
        const int row = y << 9;

        // prefetch row y+2 (overlaps this iteration's compute)
        float4 N2;
        if (i < RPW - 1)
            N2 = *(const float4*)(u + (((y + 2) & (HH - 1)) << 9) + x4);

        // periodic horizontal neighbors, all from registers
        const float leB = __shfl_sync(0xffffffffu, edge, i);
        const float riB = __shfl_sync(0xffffffffu, edge, 16 + i);
        float le = __shfl_up_sync(0xffffffffu, C.w, 1);
        float ri = __shfl_down_sync(0xffffffffu, C.x, 1);
        if (lane == 0)  le = leB;
        if (lane == 31) ri = riB;

        float4 o;
        o.x = fmaf(D, P.x + N.x + le  + C.y - 4.0f * C.x, fmaf(rho * C.x, 1.0f - C.x, C.x));
        o.y = fmaf(D, P.y + N.y + C.x + C.z - 4.0f * C.y, fmaf(rho * C.y, 1.0f - C.y, C.y));
        o.z = fmaf(D, P.z + N.z + C.y + C.w - 4.0f * C.z, fmaf(rho * C.z, 1.0f - C.z, C.z));
        o.w = fmaf(D, P.w + N.w + C.z + ri  - 4.0f * C.w, fmaf(rho * C.w, 1.0f - C.w, C.w));

        *(float4*)(v + row + x4) = o;
        ssum += (o.x + o.y) + (o.z + o.w);

        P = C; C = N; N = N2;
    }

    // --- Block-level reduce (all warps in block share batch b), 1 atomic/block ---
    #pragma unroll
    for (int o = 16; o > 0; o >>= 1) ssum += __shfl_down_sync(0xffffffffu, ssum, o);
    __shared__ float ws[WPB];
    if (lane == 0) ws[wid] = ssum;
    __syncthreads();
    if (wid == 0) {
        float s = (lane < WPB) ? ws[lane] : 0.0f;
        #pragma unroll
        for (int o = WPB / 2; o > 0; o >>= 1) s += __shfl_down_sync(0x000000ffu, s, o);
        if (lane == 0) atomicAdd(&g_sum0[(step + 1) * BATCH + b], s);
    }
}

extern "C" void kernel_launch(void* const* d_in, const int* in_sizes, int n_in,
                              void* d_out, int out_size) {
    const float* x  = (const float*)d_in[0];   // (32,4,512,512)
    const float* Wm = (const float*)d_in[1];   // (4,2)
    const float* bb = (const float*)d_in[2];   // (2,)
    const int*   t  = (const int*)d_in[3];     // (32,)
    float* out = (float*)d_out;

    zero_sums_kernel<<<1, 320>>>();

    // Copy ch1..3, reduce all per-(b,c) sums.
    init_kernel<<<dim3(PLANE / 4 / 256, BATCH * NCH), dim3(256)>>>(x, out);

    float* bufA; float* bufB;
    cudaGetSymbolAddress((void**)&bufA, g_buf0);
    cudaGetSymbolAddress((void**)&bufB, g_buf1);

    const dim3 sgrid(4 * HH / RPW / WPB, BATCH);   // (16, 32) = 512 blocks
    const dim3 sblk(WPB * 32);                     // 256
    for (int s = 0; s < NSTEPS; s++) {
        const float* src;  int sstride;
        float*       dst;  int dstride;
        if (s == 0) { src = x;  sstride = NCH * PLANE; }           // input ch0
        else        { src = ((s - 1) & 1) ? bufB : bufA; sstride = PLANE; }
        if (s == NSTEPS - 1) { dst = out; dstride = NCH * PLANE; } // output ch0
        else                 { dst = (s & 1) ? bufB : bufA; dstride = PLANE; }
        step_kernel<<<sgrid, sblk>>>(src, sstride, dst, dstride, Wm, bb, t, s);
    }
}

// round 7
// speedup vs baseline: 1.0927x; 1.0927x over previous
#include <cuda_runtime.h>

#define BATCH 32
#define NCH   4
#define HH    512
#define WW    512
#define PLANE (HH*WW)          /* 262144 */
#define NSTEPS 8
#define D_SCALE 0.2f
#define RHO_SCALE 0.1f
#define RPW 8                   /* rows per warp */
#define WPB 8                   /* warps per block */

// Ping-pong scratch for the evolving channel-0 field (2 x 32 MiB).
__device__ float g_buf0[BATCH * PLANE];
__device__ float g_buf1[BATCH * PLANE];
// Per-step channel-0 sums: slot s = sum of field entering step s.
__device__ float g_sum0[(NSTEPS + 1) * BATCH];
// Constant sums of channels 1..3 (index (c-1)*BATCH + b).
__device__ float g_sumc[3 * BATCH];

__global__ void zero_sums_kernel() {
    int i = threadIdx.x;
    if (i < (NSTEPS + 1) * BATCH) g_sum0[i] = 0.0f;
    if (i < 3 * BATCH)            g_sumc[i] = 0.0f;
}

// Copy channels 1..3 input->output, reduce per-(batch,channel) sums.
// grid = (PLANE/4/256, BATCH*NCH), block = 256. Each thread: one float4.
__global__ void init_kernel(const float* __restrict__ x, float* __restrict__ out) {
    const int p = blockIdx.y;            // plane id = b*4 + c
    const int b = p >> 2;
    const int c = p & 3;
    const int i = blockIdx.x * blockDim.x + threadIdx.x;   // 0..65535

    const float4* src = (const float4*)(x + (size_t)p * PLANE);
    float4 v = src[i];
    if (c != 0) {
        ((float4*)(out + (size_t)p * PLANE))[i] = v;
    }
    float s = (v.x + v.y) + (v.z + v.w);

    #pragma unroll
    for (int o = 16; o > 0; o >>= 1) s += __shfl_down_sync(0xffffffffu, s, o);
    __shared__ float ws[8];
    const int lane = threadIdx.x & 31;
    const int w    = threadIdx.x >> 5;
    if (lane == 0) ws[w] = s;
    __syncthreads();
    if (w == 0) {
        s = (lane < 8) ? ws[lane] : 0.0f;
        #pragma unroll
        for (int o = 4; o > 0; o >>= 1) s += __shfl_down_sync(0x000000ffu, s, o);
        if (lane == 0) {
            if (c == 0) atomicAdd(&g_sum0[0 * BATCH + b], s);
            else        atomicAdd(&g_sumc[(c - 1) * BATCH + b], s);
        }
    }
}

// One reaction-diffusion step on channel 0 for all batches.
// Warp owns a 128-float column chunk (1 float4/lane), 8-row strip.
// ALL 10 needed rows (prev halo + 8 + next halo) are loaded up-front as
// independent LDG.128 -> MLP=10 per warp; compute then runs from registers.
// Periodic edges for the 8 rows are batch-prefetched (lanes 0-7 left,
// lanes 8-15 right) -> zero in-loop loads.
// grid = (4*HH/RPW/WPB, BATCH) = (32, 32), block = 256.
__global__ __launch_bounds__(256) void step_kernel(
        const float* __restrict__ src, int src_bstride,
        float* __restrict__ dst, int dst_bstride,
        const float* __restrict__ Wm,
        const float* __restrict__ bias,
        const int* __restrict__ t, int step) {
    const int b    = blockIdx.y;
    const int lane = threadIdx.x & 31;
    const int wid  = threadIdx.x >> 5;

    const float* __restrict__ u = src + (size_t)b * src_bstride;
    float* __restrict__ v       = dst + (size_t)b * dst_bstride;

    const int w     = blockIdx.x * WPB + wid;   // 0..255
    const int chunk = w & 3;                    // x chunk (128 floats)
    const int strip = w >> 2;                   // 0..63
    const int y0    = strip * RPW;
    const int xb    = chunk << 7;               // chunk base x
    const int x4    = xb + (lane << 2);         // this lane's float4 x
    const int xl    = (xb + WW - 1) & (WW - 1); // periodic left-edge x
    const int xr    = (xb + 128) & (WW - 1);    // periodic right-edge x

    // ---- Batch all loads first: 10 row-loads + 1 edge load, all independent ----
    float4 R[RPW + 2];
    R[0] = *(const float4*)(u + (((y0 + HH - 1) & (HH - 1)) << 9) + x4);
    #pragma unroll
    for (int i = 0; i < RPW; i++)
        R[i + 1] = *(const float4*)(u + ((y0 + i) << 9) + x4);
    R[RPW + 1] = *(const float4*)(u + (((y0 + RPW) & (HH - 1)) << 9) + x4);

    // lanes 0..7: left edge of row y0+lane; lanes 8..15: right edge.
    float edge = 0.0f;
    if (lane < 16) {
        const int er = (y0 + (lane & 7)) << 9;
        edge = (lane < 8) ? u[er + xl] : u[er + xr];
    }

    // --- Derive D, rho from previous-step sums (overlaps the loads above) ---
    const float inv = 1.0f / (float)PLANE;
    const float f0 = g_sum0[step * BATCH + b] * inv;
    const float f1 = g_sumc[0 * BATCH + b] * inv;
    const float f2 = g_sumc[1 * BATCH + b] * inv;
    const float f3 = g_sumc[2 * BATCH + b] * inv;
    const float z0 = f0 * Wm[0] + f1 * Wm[2] + f2 * Wm[4] + f3 * Wm[6] + bias[0];
    const float z1 = f0 * Wm[1] + f1 * Wm[3] + f2 * Wm[5] + f3 * Wm[7] + bias[1];
    float D   = D_SCALE   / (1.0f + expf(-z0));
    float rho = RHO_SCALE / (1.0f + expf(-z1));
    if (t[b] <= step) { D = 0.0f; rho = 0.0f; }   // mask off -> exact identity

    float s0 = 0.0f, s1 = 0.0f, s2 = 0.0f, s3 = 0.0f;

    #pragma unroll
    for (int i = 0; i < RPW; i++) {
        const float4 P = R[i], C = R[i + 1], N = R[i + 2];

        const float leB = __shfl_sync(0xffffffffu, edge, i);
        const float riB = __shfl_sync(0xffffffffu, edge, 8 + i);
        float le = __shfl_up_sync(0xffffffffu, C.w, 1);
        float ri = __shfl_down_sync(0xffffffffu, C.x, 1);
        if (lane == 0)  le = leB;
        if (lane == 31) ri = riB;

        float4 o;
        o.x = fmaf(D, P.x + N.x + le  + C.y - 4.0f * C.x, fmaf(rho * C.x, 1.0f - C.x, C.x));
        o.y = fmaf(D, P.y + N.y + C.x + C.z - 4.0f * C.y, fmaf(rho * C.y, 1.0f - C.y, C.y));
        o.z = fmaf(D, P.z + N.z + C.y + C.w - 4.0f * C.z, fmaf(rho * C.z, 1.0f - C.z, C.z));
        o.w = fmaf(D, P.w + N.w + C.z + ri  - 4.0f * C.w, fmaf(rho * C.w, 1.0f - C.w, C.w));

        *(float4*)(v + ((y0 + i) << 9) + x4) = o;
        s0 += o.x; s1 += o.y; s2 += o.z; s3 += o.w;
    }

    float ssum = (s0 + s1) + (s2 + s3);

    // --- Block-level reduce (all warps in block share batch b), 1 atomic/block ---
    #pragma unroll
    for (int o = 16; o > 0; o >>= 1) ssum += __shfl_down_sync(0xffffffffu, ssum, o);
    __shared__ float ws[WPB];
    if (lane == 0) ws[wid] = ssum;
    __syncthreads();
    if (wid == 0) {
        float s = (lane < WPB) ? ws[lane] : 0.0f;
        #pragma unroll
        for (int o = WPB / 2; o > 0; o >>= 1) s += __shfl_down_sync(0x000000ffu, s, o);
        if (lane == 0) atomicAdd(&g_sum0[(step + 1) * BATCH + b], s);
    }
}

extern "C" void kernel_launch(void* const* d_in, const int* in_sizes, int n_in,
                              void* d_out, int out_size) {
    const float* x  = (const float*)d_in[0];   // (32,4,512,512)
    const float* Wm = (const float*)d_in[1];   // (4,2)
    const float* bb = (const float*)d_in[2];   // (2,)
    const int*   t  = (const int*)d_in[3];     // (32,)
    float* out = (float*)d_out;

    zero_sums_kernel<<<1, 320>>>();

    // Copy ch1..3, reduce all per-(b,c) sums.
    init_kernel<<<dim3(PLANE / 4 / 256, BATCH * NCH), dim3(256)>>>(x, out);

    float* bufA; float* bufB;
    cudaGetSymbolAddress((void**)&bufA, g_buf0);
    cudaGetSymbolAddress((void**)&bufB, g_buf1);

    const dim3 sgrid(4 * HH / RPW / WPB, BATCH);   // (32, 32) = 1024 blocks
    const dim3 sblk(WPB * 32);                     // 256
    for (int s = 0; s < NSTEPS; s++) {
        const float* src;  int sstride;
        float*       dst;  int dstride;
        if (s == 0) { src = x;  sstride = NCH * PLANE; }           // input ch0
        else        { src = ((s - 1) & 1) ? bufB : bufA; sstride = PLANE; }
        if (s == NSTEPS - 1) { dst = out; dstride = NCH * PLANE; } // output ch0
        else                 { dst = (s & 1) ? bufB : bufA; dstride = PLANE; }
        step_kernel<<<sgrid, sblk>>>(src, sstride, dst, dstride, Wm, bb, t, s);
    }
}